// round 4
// baseline (speedup 1.0000x reference)
#include <cuda_runtime.h>
#include <cstdint>

// ---------------------------------------------------------------- shapes
#define M_TOTAL 16384
#define D_DIM   4096
#define RANK    819
#define KPAD    832          // gemm2 K (rank padded to 32)
#define NPAD1   896          // Y columns = 7 * 128 (no N guards in gemm1)

// ---------------------------------------------------------------- scratch
__device__ float g_Y  [(size_t)M_TOTAL * NPAD1];  // Y = x@(U*S), tf32-rounded
__device__ float g_Bt1[(size_t)NPAD1 * D_DIM];    // (U*S)^T [n][k], rows>=819 zero
__device__ float g_Bt2[(size_t)D_DIM * KPAD];     // V^T     [n][k], k>=819 zero

// ---------------------------------------------------------------- helpers
static __device__ __forceinline__ uint32_t s2u(const void* p) {
    uint32_t a;
    asm("{ .reg .u64 t; cvta.to.shared.u64 t, %1; cvt.u32.u64 %0, t; }"
        : "=r"(a) : "l"(p));
    return a;
}
static __device__ __forceinline__ uint32_t f2tf32(float f) {
    uint32_t u;
    asm("cvt.rna.tf32.f32 %0, %1;" : "=r"(u) : "f"(f));
    return u;
}
static __device__ __forceinline__ void cp16(uint32_t dst, const void* src) {
    asm volatile("cp.async.cg.shared.global [%0], [%1], 16;"
                 :: "r"(dst), "l"(src) : "memory");
}
#define CP_COMMIT() asm volatile("cp.async.commit_group;" ::: "memory")
#define CP_WAIT1()  asm volatile("cp.async.wait_group 1;" ::: "memory")

static __device__ __forceinline__ void mma8(float c[4],
                                            uint32_t a0, uint32_t a1,
                                            uint32_t a2, uint32_t a3,
                                            uint32_t b0, uint32_t b1) {
    asm volatile(
        "mma.sync.aligned.m16n8k8.row.col.f32.tf32.tf32.f32 "
        "{%0,%1,%2,%3}, {%4,%5,%6,%7}, {%8,%9}, {%0,%1,%2,%3};"
        : "+f"(c[0]), "+f"(c[1]), "+f"(c[2]), "+f"(c[3])
        : "r"(a0), "r"(a1), "r"(a2), "r"(a3), "r"(b0), "r"(b1));
}

// smem word index for [row][k] tile, 32 words/row, XOR-swizzled 16B chunks
static __device__ __forceinline__ int swz(int row, int k) {
    return (row << 5) + ((((k >> 2) ^ (row & 7)) << 2) | (k & 3));
}

// ---------------------------------------------------------------- prep
__global__ void prep_Bt1(const float* __restrict__ U, const float* __restrict__ S,
                         float* __restrict__ Bt1) {
    __shared__ float t[32][33];
    const int k0 = blockIdx.x * 32, r0 = blockIdx.y * 32;
    const int r = r0 + threadIdx.x, k = k0 + threadIdx.y;
    float v = 0.0f;
    if (r < RANK) v = U[(size_t)k * RANK + r] * S[r];
    t[threadIdx.y][threadIdx.x] = v;
    __syncthreads();
    Bt1[(size_t)(r0 + threadIdx.y) * D_DIM + k0 + threadIdx.x] =
        __uint_as_float(f2tf32(t[threadIdx.x][threadIdx.y]));
}
__global__ void prep_Bt2(const float* __restrict__ V, float* __restrict__ Bt2) {
    __shared__ float t[32][33];
    const int k0 = blockIdx.x * 32, n0 = blockIdx.y * 32;
    const int n = n0 + threadIdx.x, k = k0 + threadIdx.y;
    float v = 0.0f;
    if (k < RANK) v = V[(size_t)k * D_DIM + n];
    t[threadIdx.y][threadIdx.x] = v;
    __syncthreads();
    Bt2[(size_t)(n0 + threadIdx.y) * KPAD + k0 + threadIdx.x] =
        __uint_as_float(f2tf32(t[threadIdx.x][threadIdx.y]));
}

// ---------------------------------------------------------------- GEMM common
#define BK 32
#define STAGES 3
#define AWORDS (128 * BK)            // 4096 words = 16KB
#define STAGEW (2 * AWORDS)          // A + B per stage (words)

// ---------------------------------------------------------------- GEMM 1
// Y[16384][896] = X[16384][4096] @ Bt1[896][4096]^T   (tf32-rounded output)
__global__ __launch_bounds__(256, 2)
void gemm1(const float* __restrict__ X, const float* __restrict__ Bt1,
           float* __restrict__ Y) {
    extern __shared__ __align__(128) uint32_t sm[];
    const int tid = threadIdx.x;
    const int lane = tid & 31, wid = tid >> 5;
    const int gid = lane >> 2, tg = lane & 3;
    const int warpM = wid >> 2, warpN = wid & 3;
    const int bm = blockIdx.y * 128, bn = blockIdx.x * 128;
    const uint32_t smu = s2u(sm);

    // per-thread cp.async chunk mapping: 4 A chunks + 4 B chunks
    const int crow = tid >> 1;                 // 0..127 (two chunk-cols/thread? no)
    // 1024 A chunks / 256 thr = 4 each: id = tid + 256*i
    float c[4][4][4];
    #pragma unroll
    for (int i = 0; i < 4; i++)
        #pragma unroll
        for (int j = 0; j < 4; j++)
            #pragma unroll
            for (int v = 0; v < 4; v++) c[i][j][v] = 0.0f;
    (void)crow;

    const int KT = D_DIM / BK;                 // 128

    // ---- loader lambda (macro-style)
    #define LOAD_STAGE1(slot, k0)                                              \
    do {                                                                       \
        const uint32_t base = smu + (slot) * (STAGEW * 4);                     \
        _Pragma("unroll")                                                      \
        for (int i = 0; i < 4; i++) {                                          \
            const int id = tid + 256 * i;                                      \
            const int row = id >> 3, cc = id & 7;                              \
            cp16(base + (((row << 3) + (cc ^ (row & 7))) << 4),                \
                 X + (size_t)(bm + row) * D_DIM + (k0) + cc * 4);              \
        }                                                                      \
        _Pragma("unroll")                                                      \
        for (int i = 0; i < 4; i++) {                                          \
            const int id = tid + 256 * i;                                      \
            const int row = id >> 3, cc = id & 7;                              \
            cp16(base + (AWORDS << 2) + (((row << 3) + (cc ^ (row & 7))) << 4),\
                 Bt1 + (size_t)(bn + row) * D_DIM + (k0) + cc * 4);            \
        }                                                                      \
    } while (0)

    LOAD_STAGE1(0, 0);  CP_COMMIT();
    LOAD_STAGE1(1, BK); CP_COMMIT();

    int slot = 0;
    for (int t = 0; t < KT; t++) {
        CP_WAIT1();
        __syncthreads();
        if (t + 2 < KT) {
            const int ns = (slot + 2 >= STAGES) ? slot + 2 - STAGES : slot + 2;
            LOAD_STAGE1(ns, (t + 2) * BK);
        }
        CP_COMMIT();

        const uint32_t* As = sm + slot * STAGEW;
        const uint32_t* Bs = As + AWORDS;
        #pragma unroll
        for (int ks = 0; ks < 4; ks++) {
            const int cb = ks * 8;
            uint32_t af[4][4];
            #pragma unroll
            for (int i = 0; i < 4; i++) {
                const int r0 = warpM * 64 + i * 16 + gid;
                af[i][0] = f2tf32(__uint_as_float(As[swz(r0,     cb + tg)]));
                af[i][1] = f2tf32(__uint_as_float(As[swz(r0 + 8, cb + tg)]));
                af[i][2] = f2tf32(__uint_as_float(As[swz(r0,     cb + tg + 4)]));
                af[i][3] = f2tf32(__uint_as_float(As[swz(r0 + 8, cb + tg + 4)]));
            }
            uint32_t bf[4][2];
            #pragma unroll
            for (int j = 0; j < 4; j++) {
                const int col = warpN * 32 + j * 8 + gid;
                bf[j][0] = Bs[swz(col, cb + tg)];
                bf[j][1] = Bs[swz(col, cb + tg + 4)];
            }
            #pragma unroll
            for (int i = 0; i < 4; i++)
                #pragma unroll
                for (int j = 0; j < 4; j++)
                    mma8(c[i][j], af[i][0], af[i][1], af[i][2], af[i][3],
                         bf[j][0], bf[j][1]);
        }
        __syncthreads();
        slot = (slot + 1 >= STAGES) ? 0 : slot + 1;
    }

    // store Y tf32-rounded (no guards)
    #pragma unroll
    for (int i = 0; i < 4; i++) {
        const int r0 = bm + warpM * 64 + i * 16 + gid;
        #pragma unroll
        for (int j = 0; j < 4; j++) {
            const int n0 = bn + warpN * 32 + j * 8 + tg * 2;
            float2 v0, v1;
            v0.x = __uint_as_float(f2tf32(c[i][j][0]));
            v0.y = __uint_as_float(f2tf32(c[i][j][1]));
            v1.x = __uint_as_float(f2tf32(c[i][j][2]));
            v1.y = __uint_as_float(f2tf32(c[i][j][3]));
            *reinterpret_cast<float2*>(Y + (size_t)r0 * NPAD1 + n0)       = v0;
            *reinterpret_cast<float2*>(Y + (size_t)(r0 + 8) * NPAD1 + n0) = v1;
        }
    }
    #undef LOAD_STAGE1
}

// ---------------------------------------------------------------- GEMM 2
// Out[16384][4096] = Y[16384][:832] @ Bt2[4096][832]^T + alpha * X
__global__ __launch_bounds__(256, 2)
void gemm2(const float* __restrict__ Yg, const float* __restrict__ Bt2,
           const float* __restrict__ X, const float* __restrict__ alphap,
           float* __restrict__ Out) {
    extern __shared__ __align__(128) uint32_t sm[];
    const int tid = threadIdx.x;
    const int lane = tid & 31, wid = tid >> 5;
    const int gid = lane >> 2, tg = lane & 3;
    const int warpM = wid >> 2, warpN = wid & 3;
    const int bm = blockIdx.y * 128, bn = blockIdx.x * 128;
    const uint32_t smu = s2u(sm);

    float c[4][4][4];
    #pragma unroll
    for (int i = 0; i < 4; i++)
        #pragma unroll
        for (int j = 0; j < 4; j++)
            #pragma unroll
            for (int v = 0; v < 4; v++) c[i][j][v] = 0.0f;

    const int KT = KPAD / BK;                  // 26

    #define LOAD_STAGE2(slot, k0)                                              \
    do {                                                                       \
        const uint32_t base = smu + (slot) * (STAGEW * 4);                     \
        _Pragma("unroll")                                                      \
        for (int i = 0; i < 4; i++) {                                          \
            const int id = tid + 256 * i;                                      \
            const int row = id >> 3, cc = id & 7;                              \
            cp16(base + (((row << 3) + (cc ^ (row & 7))) << 4),                \
                 Yg + (size_t)(bm + row) * NPAD1 + (k0) + cc * 4);             \
        }                                                                      \
        _Pragma("unroll")                                                      \
        for (int i = 0; i < 4; i++) {                                          \
            const int id = tid + 256 * i;                                      \
            const int row = id >> 3, cc = id & 7;                              \
            cp16(base + (AWORDS << 2) + (((row << 3) + (cc ^ (row & 7))) << 4),\
                 Bt2 + (size_t)(bn + row) * KPAD + (k0) + cc * 4);             \
        }                                                                      \
    } while (0)

    LOAD_STAGE2(0, 0);  CP_COMMIT();
    LOAD_STAGE2(1, BK); CP_COMMIT();

    int slot = 0;
    for (int t = 0; t < KT; t++) {
        CP_WAIT1();
        __syncthreads();
        if (t + 2 < KT) {
            const int ns = (slot + 2 >= STAGES) ? slot + 2 - STAGES : slot + 2;
            LOAD_STAGE2(ns, (t + 2) * BK);
        }
        CP_COMMIT();

        const uint32_t* As = sm + slot * STAGEW;
        const uint32_t* Bs = As + AWORDS;
        #pragma unroll
        for (int ks = 0; ks < 4; ks++) {
            const int cb = ks * 8;
            uint32_t af[4][4];
            #pragma unroll
            for (int i = 0; i < 4; i++) {
                const int r0 = warpM * 64 + i * 16 + gid;
                af[i][0] = As[swz(r0,     cb + tg)];
                af[i][1] = As[swz(r0 + 8, cb + tg)];
                af[i][2] = As[swz(r0,     cb + tg + 4)];
                af[i][3] = As[swz(r0 + 8, cb + tg + 4)];
            }
            uint32_t bf[4][2];
            #pragma unroll
            for (int j = 0; j < 4; j++) {
                const int col = warpN * 32 + j * 8 + gid;
                bf[j][0] = Bs[swz(col, cb + tg)];
                bf[j][1] = Bs[swz(col, cb + tg + 4)];
            }
            #pragma unroll
            for (int i = 0; i < 4; i++)
                #pragma unroll
                for (int j = 0; j < 4; j++)
                    mma8(c[i][j], af[i][0], af[i][1], af[i][2], af[i][3],
                         bf[j][0], bf[j][1]);
        }
        __syncthreads();
        slot = (slot + 1 >= STAGES) ? 0 : slot + 1;
    }

    const float alpha = *alphap;
    #pragma unroll
    for (int i = 0; i < 4; i++) {
        const int r0 = bm + warpM * 64 + i * 16 + gid;
        #pragma unroll
        for (int j = 0; j < 4; j++) {
            const int n0 = bn + warpN * 32 + j * 8 + tg * 2;
            {
                const size_t off = (size_t)r0 * D_DIM + n0;
                float2 xv = *reinterpret_cast<const float2*>(X + off);
                float2 ov;
                ov.x = fmaf(alpha, xv.x, c[i][j][0]);
                ov.y = fmaf(alpha, xv.y, c[i][j][1]);
                *reinterpret_cast<float2*>(Out + off) = ov;
            }
            {
                const size_t off = (size_t)(r0 + 8) * D_DIM + n0;
                float2 xv = *reinterpret_cast<const float2*>(X + off);
                float2 ov;
                ov.x = fmaf(alpha, xv.x, c[i][j][2]);
                ov.y = fmaf(alpha, xv.y, c[i][j][3]);
                *reinterpret_cast<float2*>(Out + off) = ov;
            }
        }
    }
    #undef LOAD_STAGE2
}

// ---------------------------------------------------------------- launch
extern "C" void kernel_launch(void* const* d_in, const int* in_sizes, int n_in,
                              void* d_out, int out_size) {
    const float* x     = (const float*)d_in[0];
    const float* U     = (const float*)d_in[1];
    const float* S     = (const float*)d_in[2];
    const float* V     = (const float*)d_in[3];
    const float* alpha = (const float*)d_in[4];
    float* out = (float*)d_out;

    float *Yp, *B1p, *B2p;
    cudaGetSymbolAddress((void**)&Yp,  g_Y);
    cudaGetSymbolAddress((void**)&B1p, g_Bt1);
    cudaGetSymbolAddress((void**)&B2p, g_Bt2);

    constexpr int SMEM = STAGES * STAGEW * 4;   // 3 * 32KB = 98304
    cudaFuncSetAttribute(gemm1, cudaFuncAttributeMaxDynamicSharedMemorySize, SMEM);
    cudaFuncSetAttribute(gemm2, cudaFuncAttributeMaxDynamicSharedMemorySize, SMEM);

    prep_Bt1<<<dim3(D_DIM / 32, NPAD1 / 32), dim3(32, 32)>>>(U, S, B1p);
    prep_Bt2<<<dim3(KPAD / 32, D_DIM / 32), dim3(32, 32)>>>(V, B2p);

    gemm1<<<dim3(NPAD1 / 128, M_TOTAL / 128), 256, SMEM>>>(x, B1p, Yp);
    gemm2<<<dim3(D_DIM / 128, M_TOTAL / 128), 256, SMEM>>>(Yp, B2p, x, alpha, out);
}

// round 5
// speedup vs baseline: 1.5136x; 1.5136x over previous
#include <cuda_runtime.h>
#include <cstdint>

// ---------------------------------------------------------------- shapes
#define M_TOTAL 16384
#define D_DIM   4096
#define RANK    819
#define KPAD    832          // gemm2 K (rank padded to 32)
#define NPAD1   896          // Y columns = 7 * 128

// ---------------------------------------------------------------- scratch
__device__ float g_Xr [(size_t)M_TOTAL * D_DIM];  // rna(x)
__device__ float g_Y  [(size_t)M_TOTAL * NPAD1];  // Y = x@(U*S), rna-rounded
__device__ float g_B1 [(size_t)D_DIM * NPAD1];    // rna(U*S)  [k][n], n>=819 zero
__device__ float g_B2 [(size_t)KPAD * D_DIM];     // rna(V)    [k][n], k>=819 zero

// ---------------------------------------------------------------- helpers
static __device__ __forceinline__ uint32_t s2u(const void* p) {
    uint32_t a;
    asm("{ .reg .u64 t; cvta.to.shared.u64 t, %1; cvt.u32.u64 %0, t; }"
        : "=r"(a) : "l"(p));
    return a;
}
static __device__ __forceinline__ uint32_t f2tf32(float f) {
    uint32_t u;
    asm("cvt.rna.tf32.f32 %0, %1;" : "=r"(u) : "f"(f));
    return u;
}
static __device__ __forceinline__ void cp16(uint32_t dst, const void* src) {
    asm volatile("cp.async.cg.shared.global [%0], [%1], 16;"
                 :: "r"(dst), "l"(src) : "memory");
}
#define CP_COMMIT() asm volatile("cp.async.commit_group;" ::: "memory")
#define CP_WAIT1()  asm volatile("cp.async.wait_group 1;" ::: "memory")

static __device__ __forceinline__ void mma8(float c[4],
                                            uint32_t a0, uint32_t a1,
                                            uint32_t a2, uint32_t a3,
                                            uint32_t b0, uint32_t b1) {
    asm volatile(
        "mma.sync.aligned.m16n8k8.row.col.f32.tf32.tf32.f32 "
        "{%0,%1,%2,%3}, {%4,%5,%6,%7}, {%8,%9}, {%0,%1,%2,%3};"
        : "+f"(c[0]), "+f"(c[1]), "+f"(c[2]), "+f"(c[3])
        : "r"(a0), "r"(a1), "r"(a2), "r"(a3), "r"(b0), "r"(b1));
}

// ---------------------------------------------------------------- prep
__global__ void prep_X(const float4* __restrict__ X, float4* __restrict__ Xr) {
    const size_t i = (size_t)blockIdx.x * blockDim.x + threadIdx.x;
    float4 v = X[i];
    v.x = __uint_as_float(f2tf32(v.x));
    v.y = __uint_as_float(f2tf32(v.y));
    v.z = __uint_as_float(f2tf32(v.z));
    v.w = __uint_as_float(f2tf32(v.w));
    Xr[i] = v;
}
__global__ void prep_B1(const float* __restrict__ U, const float* __restrict__ S,
                        float* __restrict__ B1) {
    const size_t id = (size_t)blockIdx.x * blockDim.x + threadIdx.x;
    const int n = (int)(id % NPAD1), k = (int)(id / NPAD1);
    float v = 0.0f;
    if (n < RANK) v = __uint_as_float(f2tf32(U[(size_t)k * RANK + n] * S[n]));
    B1[id] = v;
}
__global__ void prep_B2(const float* __restrict__ V, float* __restrict__ B2) {
    const size_t id = (size_t)blockIdx.x * blockDim.x + threadIdx.x;
    const int n = (int)(id & (D_DIM - 1)), k = (int)(id / D_DIM);
    float v = 0.0f;
    if (k < RANK) v = __uint_as_float(f2tf32(V[(size_t)k * D_DIM + n]));
    B2[id] = v;
}

// ---------------------------------------------------------------- GEMM tiles
#define BK 32
#define STAGES 3
#define ASTRIDE 36                       // words per A row (pad 4), 144B aligned
#define BSTRIDE 136                      // words per B row (pad 8), 544B aligned
#define AW (128 * ASTRIDE)               // 4608 words
#define BW (BK * BSTRIDE)                // 4352 words
#define SW (AW + BW)                     // 8960 words / stage
#define SMEM_BYTES (STAGES * SW * 4)     // 107520

// Generic pipelined 128x128 GEMM body.  A: [m][k] rowsrc, B: [k][n] rowsrc.
template <int KT, int LDA, int LDB, bool ROUND_OUT, bool ADD_X>
__device__ __forceinline__ void gemm_body(
    const float* __restrict__ Ag, const float* __restrict__ Bg,
    const float* __restrict__ Xg, const float* __restrict__ alphap,
    float* __restrict__ Og, int ldo)
{
    extern __shared__ __align__(128) uint32_t sm[];
    const int tid = threadIdx.x;
    const int lane = tid & 31, wid = tid >> 5;
    const int gid = lane >> 2, tg = lane & 3;
    const int warpM = wid >> 2, warpN = wid & 3;
    const int bm = blockIdx.y * 128, bn = blockIdx.x * 128;
    const uint32_t smu = s2u(sm);

    // cp.async mappings (per thread: 4 A chunks + 4 B chunks)
    const int arow = tid >> 1;                 // with +128: covers 0..127 twice? no:
    // A: 1024 chunks: c = tid + 256*i, row=c>>3 (0..127), cc=c&7
    // B: 1024 chunks: c = tid + 256*i, row=c>>5 (0..31),  cc=c&31
    (void)arow;

    float c[4][4][4];
    #pragma unroll
    for (int i = 0; i < 4; i++)
        #pragma unroll
        for (int j = 0; j < 4; j++)
            #pragma unroll
            for (int v = 0; v < 4; v++) c[i][j][v] = 0.0f;

    #define LOADST(slot, k0)                                                   \
    do {                                                                       \
        const uint32_t base = smu + (slot) * (SW * 4);                         \
        _Pragma("unroll")                                                      \
        for (int i = 0; i < 4; i++) {                                          \
            const int id = tid + 256 * i;                                      \
            const int row = id >> 3, cc = id & 7;                              \
            cp16(base + (row * ASTRIDE + cc * 4) * 4,                          \
                 Ag + (size_t)(bm + row) * LDA + (k0) + cc * 4);               \
        }                                                                      \
        _Pragma("unroll")                                                      \
        for (int i = 0; i < 4; i++) {                                          \
            const int id = tid + 256 * i;                                      \
            const int row = id >> 5, cc = id & 31;                             \
            cp16(base + (AW + row * BSTRIDE + cc * 4) * 4,                     \
                 Bg + (size_t)((k0) + row) * LDB + bn + cc * 4);               \
        }                                                                      \
    } while (0)

    LOADST(0, 0);  CP_COMMIT();
    LOADST(1, BK); CP_COMMIT();

    int slot = 0;
    for (int t = 0; t < KT; t++) {
        CP_WAIT1();
        __syncthreads();
        if (t + 2 < KT) {
            const int ns = (slot + 2 >= STAGES) ? slot + 2 - STAGES : slot + 2;
            LOADST(ns, (t + 2) * BK);
        }
        CP_COMMIT();

        const uint32_t* As = sm + slot * SW;
        const uint32_t* Bs = As + AW;
        #pragma unroll
        for (int ks = 0; ks < 4; ks++) {
            const int cb = ks * 8;
            uint32_t af[4][4];
            #pragma unroll
            for (int i = 0; i < 4; i++) {
                const int r0 = warpM * 64 + i * 16 + gid;
                af[i][0] = As[r0 * ASTRIDE + cb + tg];
                af[i][1] = As[(r0 + 8) * ASTRIDE + cb + tg];
                af[i][2] = As[r0 * ASTRIDE + cb + tg + 4];
                af[i][3] = As[(r0 + 8) * ASTRIDE + cb + tg + 4];
            }
            uint32_t bf[4][2];
            #pragma unroll
            for (int j = 0; j < 4; j++) {
                const int col = warpN * 32 + j * 8 + gid;
                bf[j][0] = Bs[(cb + tg) * BSTRIDE + col];
                bf[j][1] = Bs[(cb + tg + 4) * BSTRIDE + col];
            }
            #pragma unroll
            for (int i = 0; i < 4; i++)
                #pragma unroll
                for (int j = 0; j < 4; j++)
                    mma8(c[i][j], af[i][0], af[i][1], af[i][2], af[i][3],
                         bf[j][0], bf[j][1]);
        }
        __syncthreads();
        slot = (slot + 1 >= STAGES) ? 0 : slot + 1;
    }
    #undef LOADST

    float alpha = 0.0f;
    if (ADD_X) alpha = *alphap;

    #pragma unroll
    for (int i = 0; i < 4; i++) {
        const int r0 = bm + warpM * 64 + i * 16 + gid;
        #pragma unroll
        for (int j = 0; j < 4; j++) {
            const int n0 = bn + warpN * 32 + j * 8 + tg * 2;
            #pragma unroll
            for (int h = 0; h < 2; h++) {
                const size_t off = (size_t)(r0 + 8 * h) * ldo + n0;
                float2 ov;
                if (ADD_X) {
                    float2 xv = *reinterpret_cast<const float2*>(Xg + off);
                    ov.x = fmaf(alpha, xv.x, c[i][j][2 * h + 0]);
                    ov.y = fmaf(alpha, xv.y, c[i][j][2 * h + 1]);
                } else if (ROUND_OUT) {
                    ov.x = __uint_as_float(f2tf32(c[i][j][2 * h + 0]));
                    ov.y = __uint_as_float(f2tf32(c[i][j][2 * h + 1]));
                } else {
                    ov.x = c[i][j][2 * h + 0];
                    ov.y = c[i][j][2 * h + 1];
                }
                *reinterpret_cast<float2*>(Og + off) = ov;
            }
        }
    }
}

// GEMM1: Y[16384][896] = Xr @ B1,  KT = 4096/32 = 128
__global__ __launch_bounds__(256, 2)
void gemm1(const float* __restrict__ Xr, const float* __restrict__ B1,
           float* __restrict__ Y) {
    gemm_body<D_DIM / BK, D_DIM, NPAD1, true, false>(Xr, B1, nullptr, nullptr,
                                                     Y, NPAD1);
}

// GEMM2: Out = Y[:, :832] @ B2 + alpha * X,  KT = 832/32 = 26
__global__ __launch_bounds__(256, 2)
void gemm2(const float* __restrict__ Yg, const float* __restrict__ B2,
           const float* __restrict__ X, const float* __restrict__ alphap,
           float* __restrict__ Out) {
    gemm_body<KPAD / BK, NPAD1, D_DIM, false, true>(Yg, B2, X, alphap,
                                                    Out, D_DIM);
}

// ---------------------------------------------------------------- launch
extern "C" void kernel_launch(void* const* d_in, const int* in_sizes, int n_in,
                              void* d_out, int out_size) {
    const float* x     = (const float*)d_in[0];
    const float* U     = (const float*)d_in[1];
    const float* S     = (const float*)d_in[2];
    const float* V     = (const float*)d_in[3];
    const float* alpha = (const float*)d_in[4];
    float* out = (float*)d_out;

    float *Xrp, *Yp, *B1p, *B2p;
    cudaGetSymbolAddress((void**)&Xrp, g_Xr);
    cudaGetSymbolAddress((void**)&Yp,  g_Y);
    cudaGetSymbolAddress((void**)&B1p, g_B1);
    cudaGetSymbolAddress((void**)&B2p, g_B2);

    cudaFuncSetAttribute(gemm1, cudaFuncAttributeMaxDynamicSharedMemorySize,
                         SMEM_BYTES);
    cudaFuncSetAttribute(gemm2, cudaFuncAttributeMaxDynamicSharedMemorySize,
                         SMEM_BYTES);

    // Prep passes (elementwise, coalesced)
    prep_X<<<(M_TOTAL * (size_t)D_DIM / 4) / 256, 256>>>((const float4*)x,
                                                         (float4*)Xrp);
    prep_B1<<<((size_t)D_DIM * NPAD1) / 256, 256>>>(U, S, B1p);
    prep_B2<<<((size_t)KPAD * D_DIM) / 256, 256>>>(V, B2p);

    gemm1<<<dim3(NPAD1 / 128, M_TOTAL / 128), 256, SMEM_BYTES>>>(Xrp, B1p, Yp);
    gemm2<<<dim3(D_DIM / 128, M_TOTAL / 128), 256, SMEM_BYTES>>>(Yp, B2p, x,
                                                                 alpha, out);
}

// round 6
// speedup vs baseline: 1.5237x; 1.0067x over previous
#include <cuda_runtime.h>
#include <cstdint>

// ---------------------------------------------------------------- shapes
#define M_TOTAL 16384
#define D_DIM   4096
#define RANK    819
#define KPAD    832          // gemm2 K (rank padded to 32)
#define NPAD1   896          // Y columns = 7 * 128

// ---------------------------------------------------------------- scratch
__device__ float g_Xr [(size_t)M_TOTAL * D_DIM];  // rna(x)
__device__ float g_Y  [(size_t)M_TOTAL * NPAD1];  // Y = x@(U*S), rna-rounded
__device__ float g_B1 [(size_t)D_DIM * NPAD1];    // rna(U*S)  [k][n], n>=819 zero
__device__ float g_B2 [(size_t)KPAD * D_DIM];     // rna(V)    [k][n], k>=819 zero

// ---------------------------------------------------------------- helpers
static __device__ __forceinline__ uint32_t s2u(const void* p) {
    uint32_t a;
    asm("{ .reg .u64 t; cvta.to.shared.u64 t, %1; cvt.u32.u64 %0, t; }"
        : "=r"(a) : "l"(p));
    return a;
}
static __device__ __forceinline__ uint32_t f2tf32(float f) {
    uint32_t u;
    asm("cvt.rna.tf32.f32 %0, %1;" : "=r"(u) : "f"(f));
    return u;
}
static __device__ __forceinline__ void cp16(uint32_t dst, const void* src) {
    asm volatile("cp.async.cg.shared.global [%0], [%1], 16;"
                 :: "r"(dst), "l"(src) : "memory");
}
#define CP_COMMIT() asm volatile("cp.async.commit_group;" ::: "memory")
#define CP_WAIT1()  asm volatile("cp.async.wait_group 1;" ::: "memory")

static __device__ __forceinline__ void mma8(float c[4],
                                            uint32_t a0, uint32_t a1,
                                            uint32_t a2, uint32_t a3,
                                            uint32_t b0, uint32_t b1) {
    asm volatile(
        "mma.sync.aligned.m16n8k8.row.col.f32.tf32.tf32.f32 "
        "{%0,%1,%2,%3}, {%4,%5,%6,%7}, {%8,%9}, {%0,%1,%2,%3};"
        : "+f"(c[0]), "+f"(c[1]), "+f"(c[2]), "+f"(c[3])
        : "r"(a0), "r"(a1), "r"(a2), "r"(a3), "r"(b0), "r"(b1));
}

// ---------------------------------------------------------------- prep
__global__ void prep_X(const float4* __restrict__ X, float4* __restrict__ Xr) {
    const size_t i = (size_t)blockIdx.x * blockDim.x + threadIdx.x;
    float4 v = X[i];
    v.x = __uint_as_float(f2tf32(v.x));
    v.y = __uint_as_float(f2tf32(v.y));
    v.z = __uint_as_float(f2tf32(v.z));
    v.w = __uint_as_float(f2tf32(v.w));
    Xr[i] = v;
}
__global__ void prep_B1(const float* __restrict__ U, const float* __restrict__ S,
                        float* __restrict__ B1) {
    const size_t id = (size_t)blockIdx.x * blockDim.x + threadIdx.x;
    const int n = (int)(id % NPAD1), k = (int)(id / NPAD1);
    float v = 0.0f;
    if (n < RANK) v = __uint_as_float(f2tf32(U[(size_t)k * RANK + n] * S[n]));
    B1[id] = v;
}
__global__ void prep_B2(const float* __restrict__ V, float* __restrict__ B2) {
    const size_t id = (size_t)blockIdx.x * blockDim.x + threadIdx.x;
    const int n = (int)(id & (D_DIM - 1)), k = (int)(id / D_DIM);
    float v = 0.0f;
    if (k < RANK) v = __uint_as_float(f2tf32(V[(size_t)k * D_DIM + n]));
    B2[id] = v;
}

// ---------------------------------------------------------------- GEMM body
// CTA tile BM x BN, 8 warps arranged WM x (8/WM), warp tile 64x64.
// A: [m][k] row-major (LDA), B: [k][n] row-major (LDB). BK=32, 3 stages.
#define BK 32
#define STAGES 3

template <int BM, int BN, int WM, int KT, int LDA, int LDB,
          bool ROUND_OUT, bool ADD_X>
__device__ __forceinline__ void gemm_body(
    const float* __restrict__ Ag, const float* __restrict__ Bg,
    const float* __restrict__ Xg, const float* __restrict__ alphap,
    float* __restrict__ Og, int ldo)
{
    constexpr int ASTRIDE = BK + 4;            // 36 words, conflict-free
    constexpr int BSTRIDE = BN + 8;            // conflict-free
    constexpr int AW = BM * ASTRIDE;
    constexpr int BW = BK * BSTRIDE;
    constexpr int SW = AW + BW;
    constexpr int ACH = BM * 8;                // A 16B chunks per stage
    constexpr int BCH = BK * (BN / 4);         // B 16B chunks per stage
    constexpr int WN = 8 / WM;
    constexpr int BNC = BN / 4;                // B chunks per k-row (pow2)

    extern __shared__ __align__(128) uint32_t sm[];
    const int tid = threadIdx.x;
    const int lane = tid & 31, wid = tid >> 5;
    const int gid = lane >> 2, tg = lane & 3;
    const int warpM = wid / WN, warpN = wid % WN;
    const int bm = blockIdx.y * BM, bn = blockIdx.x * BN;
    const uint32_t smu = s2u(sm);

    float c[4][8][4];
    #pragma unroll
    for (int i = 0; i < 4; i++)
        #pragma unroll
        for (int j = 0; j < 8; j++)
            #pragma unroll
            for (int v = 0; v < 4; v++) c[i][j][v] = 0.0f;

    #define LOADST(slot, k0)                                                   \
    do {                                                                       \
        const uint32_t base = smu + (slot) * (SW * 4);                         \
        _Pragma("unroll")                                                      \
        for (int i = 0; i < (ACH + BCH) / 256; i++) {                          \
            const int id = tid + 256 * i;                                      \
            if (id < ACH) {                                                    \
                const int row = id >> 3, cc = id & 7;                          \
                cp16(base + (row * ASTRIDE + cc * 4) * 4,                      \
                     Ag + (size_t)(bm + row) * LDA + (k0) + cc * 4);           \
            } else {                                                           \
                const int id2 = id - ACH;                                      \
                const int row = id2 / BNC, cc = id2 % BNC;                     \
                cp16(base + (AW + row * BSTRIDE + cc * 4) * 4,                 \
                     Bg + (size_t)((k0) + row) * LDB + bn + cc * 4);           \
            }                                                                  \
        }                                                                      \
    } while (0)

    LOADST(0, 0);  CP_COMMIT();
    LOADST(1, BK); CP_COMMIT();

    int slot = 0;
    for (int t = 0; t < KT; t++) {
        CP_WAIT1();
        __syncthreads();
        if (t + 2 < KT) {
            const int ns = (slot + 2 >= STAGES) ? slot + 2 - STAGES : slot + 2;
            LOADST(ns, (t + 2) * BK);
        }
        CP_COMMIT();

        const uint32_t* As = sm + slot * SW;
        const uint32_t* Bs = As + AW;
        #pragma unroll
        for (int ks = 0; ks < 4; ks++) {
            const int cb = ks * 8;
            uint32_t af[4][4];
            #pragma unroll
            for (int i = 0; i < 4; i++) {
                const int r0 = warpM * 64 + i * 16 + gid;
                af[i][0] = As[r0 * ASTRIDE + cb + tg];
                af[i][1] = As[(r0 + 8) * ASTRIDE + cb + tg];
                af[i][2] = As[r0 * ASTRIDE + cb + tg + 4];
                af[i][3] = As[(r0 + 8) * ASTRIDE + cb + tg + 4];
            }
            #pragma unroll
            for (int j = 0; j < 8; j++) {
                const int col = warpN * 64 + j * 8 + gid;
                const uint32_t b0 = Bs[(cb + tg) * BSTRIDE + col];
                const uint32_t b1 = Bs[(cb + tg + 4) * BSTRIDE + col];
                #pragma unroll
                for (int i = 0; i < 4; i++)
                    mma8(c[i][j], af[i][0], af[i][1], af[i][2], af[i][3],
                         b0, b1);
            }
        }
        __syncthreads();
        slot = (slot + 1 >= STAGES) ? 0 : slot + 1;
    }
    #undef LOADST

    float alpha = 0.0f;
    if (ADD_X) alpha = *alphap;

    #pragma unroll
    for (int i = 0; i < 4; i++) {
        const int r0 = bm + warpM * 64 + i * 16 + gid;
        #pragma unroll
        for (int j = 0; j < 8; j++) {
            const int n0 = bn + warpN * 64 + j * 8 + tg * 2;
            #pragma unroll
            for (int h = 0; h < 2; h++) {
                const size_t off = (size_t)(r0 + 8 * h) * ldo + n0;
                float2 ov;
                if (ADD_X) {
                    float2 xv = *reinterpret_cast<const float2*>(Xg + off);
                    ov.x = fmaf(alpha, xv.x, c[i][j][2 * h + 0]);
                    ov.y = fmaf(alpha, xv.y, c[i][j][2 * h + 1]);
                } else if (ROUND_OUT) {
                    ov.x = __uint_as_float(f2tf32(c[i][j][2 * h + 0]));
                    ov.y = __uint_as_float(f2tf32(c[i][j][2 * h + 1]));
                } else {
                    ov.x = c[i][j][2 * h + 0];
                    ov.y = c[i][j][2 * h + 1];
                }
                *reinterpret_cast<float2*>(Og + off) = ov;
            }
        }
    }
}

// GEMM1: Y[16384][896] = Xr @ B1.  CTA 256x128 (4M x 2N warps), KT=128.
__global__ __launch_bounds__(256, 1)
void gemm1(const float* __restrict__ Xr, const float* __restrict__ B1,
           float* __restrict__ Y) {
    gemm_body<256, 128, 4, D_DIM / BK, D_DIM, NPAD1, true, false>(
        Xr, B1, nullptr, nullptr, Y, NPAD1);
}

// GEMM2: Out = Y[:, :832] @ B2 + alpha * X.  CTA 128x256 (2M x 4N), KT=26.
__global__ __launch_bounds__(256, 1)
void gemm2(const float* __restrict__ Yg, const float* __restrict__ B2,
           const float* __restrict__ X, const float* __restrict__ alphap,
           float* __restrict__ Out) {
    gemm_body<128, 256, 2, KPAD / BK, NPAD1, D_DIM, false, true>(
        Yg, B2, X, alphap, Out, D_DIM);
}

// ---------------------------------------------------------------- launch
extern "C" void kernel_launch(void* const* d_in, const int* in_sizes, int n_in,
                              void* d_out, int out_size) {
    const float* x     = (const float*)d_in[0];
    const float* U     = (const float*)d_in[1];
    const float* S     = (const float*)d_in[2];
    const float* V     = (const float*)d_in[3];
    const float* alpha = (const float*)d_in[4];
    float* out = (float*)d_out;

    float *Xrp, *Yp, *B1p, *B2p;
    cudaGetSymbolAddress((void**)&Xrp, g_Xr);
    cudaGetSymbolAddress((void**)&Yp,  g_Y);
    cudaGetSymbolAddress((void**)&B1p, g_B1);
    cudaGetSymbolAddress((void**)&B2p, g_B2);

    // smem: stage = BM*36 + 32*(BN+8) words
    constexpr int SMEM1 = STAGES * (256 * 36 + 32 * 136) * 4;   // 162816
    constexpr int SMEM2 = STAGES * (128 * 36 + 32 * 264) * 4;   // 156672
    cudaFuncSetAttribute(gemm1, cudaFuncAttributeMaxDynamicSharedMemorySize,
                         SMEM1);
    cudaFuncSetAttribute(gemm2, cudaFuncAttributeMaxDynamicSharedMemorySize,
                         SMEM2);

    prep_X<<<(M_TOTAL * (size_t)D_DIM / 4) / 256, 256>>>((const float4*)x,
                                                         (float4*)Xrp);
    prep_B1<<<((size_t)D_DIM * NPAD1) / 256, 256>>>(U, S, B1p);
    prep_B2<<<((size_t)KPAD * D_DIM) / 256, 256>>>(V, B2p);

    gemm1<<<dim3(NPAD1 / 128, M_TOTAL / 256), 256, SMEM1>>>(Xrp, B1p, Yp);
    gemm2<<<dim3(D_DIM / 256, M_TOTAL / 128), 256, SMEM2>>>(Yp, B2p, x,
                                                            alpha, out);
}

// round 7
// speedup vs baseline: 1.5590x; 1.0231x over previous
#include <cuda_runtime.h>
#include <cstdint>

// ---------------------------------------------------------------- shapes
#define M_TOTAL 16384
#define D_DIM   4096
#define RANK    819
#define KPAD    832          // gemm2 K (rank padded to 64)
#define NPAD1   896          // Y columns = 7 * 128

// ---------------------------------------------------------------- scratch
__device__ float g_Xr [(size_t)M_TOTAL * D_DIM];  // rna(x)
__device__ float g_Y  [(size_t)M_TOTAL * NPAD1];  // Y, rna-rounded
__device__ float g_B1 [(size_t)D_DIM * NPAD1];    // rna(U*S)  [k][n]
__device__ float g_B2 [(size_t)KPAD * D_DIM];     // rna(V)    [k][n]

// ---------------------------------------------------------------- helpers
static __device__ __forceinline__ uint32_t s2u(const void* p) {
    uint32_t a;
    asm("{ .reg .u64 t; cvta.to.shared.u64 t, %1; cvt.u32.u64 %0, t; }"
        : "=r"(a) : "l"(p));
    return a;
}
static __device__ __forceinline__ uint32_t f2tf32(float f) {
    uint32_t u;
    asm("cvt.rna.tf32.f32 %0, %1;" : "=r"(u) : "f"(f));
    return u;
}
static __device__ __forceinline__ void cp16(uint32_t dst, const void* src) {
    asm volatile("cp.async.cg.shared.global [%0], [%1], 16;"
                 :: "r"(dst), "l"(src) : "memory");
}
#define CP_COMMIT() asm volatile("cp.async.commit_group;" ::: "memory")
#define CP_WAIT0()  asm volatile("cp.async.wait_group 0;" ::: "memory")

static __device__ __forceinline__ void mma8(float c[4],
                                            uint32_t a0, uint32_t a1,
                                            uint32_t a2, uint32_t a3,
                                            uint32_t b0, uint32_t b1) {
    asm volatile(
        "mma.sync.aligned.m16n8k8.row.col.f32.tf32.tf32.f32 "
        "{%0,%1,%2,%3}, {%4,%5,%6,%7}, {%8,%9}, {%0,%1,%2,%3};"
        : "+f"(c[0]), "+f"(c[1]), "+f"(c[2]), "+f"(c[3])
        : "r"(a0), "r"(a1), "r"(a2), "r"(a3), "r"(b0), "r"(b1));
}

// ---------------------------------------------------------------- prep
__global__ void prep_X(const float4* __restrict__ X, float4* __restrict__ Xr) {
    const size_t i = (size_t)blockIdx.x * blockDim.x + threadIdx.x;
    float4 v = X[i];
    v.x = __uint_as_float(f2tf32(v.x));
    v.y = __uint_as_float(f2tf32(v.y));
    v.z = __uint_as_float(f2tf32(v.z));
    v.w = __uint_as_float(f2tf32(v.w));
    Xr[i] = v;
}
__global__ void prep_B1(const float* __restrict__ U, const float* __restrict__ S,
                        float* __restrict__ B1) {
    const size_t id = (size_t)blockIdx.x * blockDim.x + threadIdx.x;
    const int n = (int)(id % NPAD1), k = (int)(id / NPAD1);
    float v = 0.0f;
    if (n < RANK) v = __uint_as_float(f2tf32(U[(size_t)k * RANK + n] * S[n]));
    B1[id] = v;
}
__global__ void prep_B2(const float* __restrict__ V, float* __restrict__ B2) {
    const size_t id = (size_t)blockIdx.x * blockDim.x + threadIdx.x;
    const int n = (int)(id & (D_DIM - 1)), k = (int)(id / D_DIM);
    float v = 0.0f;
    if (k < RANK) v = __uint_as_float(f2tf32(V[(size_t)k * D_DIM + n]));
    B2[id] = v;
}

// ---------------------------------------------------------------- GEMM body
// CTA tile BM x BN, 8 warps WM x (8/WM), warp tile 64x64. BK=64, 2 stages.
#define BKT 64

template <int BM, int BN, int WM, int KT, int LDA, int LDB,
          bool ROUND_OUT, bool ADD_X>
__device__ __forceinline__ void gemm_body(
    const float* __restrict__ Ag, const float* __restrict__ Bg,
    const float* __restrict__ Xg, const float* __restrict__ alphap,
    float* __restrict__ Og, int ldo)
{
    constexpr int ASTRIDE = BKT + 4;           // 68 words, conflict-free
    constexpr int BSTRIDE = BN + 8;            // conflict-free
    constexpr int AW = BM * ASTRIDE;
    constexpr int BW = BKT * BSTRIDE;
    constexpr int SW = AW + BW;
    constexpr int ACH = BM * (BKT / 4);        // A 16B chunks / stage
    constexpr int BCH = BKT * (BN / 4);        // B 16B chunks / stage
    constexpr int WN = 8 / WM;
    constexpr int ACR = BKT / 4;               // A chunks per row (16)
    constexpr int BCR = BN / 4;                // B chunks per k-row

    extern __shared__ __align__(128) uint32_t sm[];
    const int tid = threadIdx.x;
    const int lane = tid & 31, wid = tid >> 5;
    const int gid = lane >> 2, tg = lane & 3;
    const int warpM = wid / WN, warpN = wid % WN;
    const int bm = blockIdx.y * BM, bn = blockIdx.x * BN;
    const uint32_t smu = s2u(sm);

    float alpha = 0.0f;
    if (ADD_X) alpha = *alphap;

    float c[4][8][4];
    #pragma unroll
    for (int i = 0; i < 4; i++)
        #pragma unroll
        for (int j = 0; j < 8; j++)
            #pragma unroll
            for (int v = 0; v < 4; v++) c[i][j][v] = 0.0f;

    #define LOADST(slot, k0)                                                   \
    do {                                                                       \
        const uint32_t base = smu + (slot) * (SW * 4);                         \
        _Pragma("unroll")                                                      \
        for (int ii = 0; ii < (ACH + BCH) / 256; ii++) {                       \
            const int id = tid + 256 * ii;                                     \
            if (id < ACH) {                                                    \
                const int row = id / ACR, cc = id % ACR;                       \
                cp16(base + (row * ASTRIDE + cc * 4) * 4,                      \
                     Ag + (size_t)(bm + row) * LDA + (k0) + cc * 4);           \
            } else {                                                           \
                const int id2 = id - ACH;                                      \
                const int row = id2 / BCR, cc = id2 % BCR;                     \
                cp16(base + (AW + row * BSTRIDE + cc * 4) * 4,                 \
                     Bg + (size_t)((k0) + row) * LDB + bn + cc * 4);           \
            }                                                                  \
        }                                                                      \
    } while (0)

    // prologue: load tile 0 into slot 0
    LOADST(0, 0);
    CP_COMMIT();

    int slot = 0;
    for (int t = 0; t < KT; t++) {
        CP_WAIT0();            // tile t resident (only pending group)
        __syncthreads();       // all reads of the other slot (iter t-1) done
        if (t + 1 < KT) LOADST(slot ^ 1, (t + 1) * BKT);
        CP_COMMIT();

        const uint32_t* As = sm + slot * SW;
        const uint32_t* Bs = As + AW;

        // fragment double-buffer across the 8 ks-steps
        uint32_t af[2][4][4];
        {
            #pragma unroll
            for (int i = 0; i < 4; i++) {
                const int r0 = warpM * 64 + i * 16 + gid;
                af[0][i][0] = As[r0 * ASTRIDE + tg];
                af[0][i][1] = As[(r0 + 8) * ASTRIDE + tg];
                af[0][i][2] = As[r0 * ASTRIDE + tg + 4];
                af[0][i][3] = As[(r0 + 8) * ASTRIDE + tg + 4];
            }
        }
        #pragma unroll
        for (int ks = 0; ks < 8; ks++) {
            const int cur = ks & 1, nxt = cur ^ 1;
            if (ks < 7) {
                const int cb = (ks + 1) * 8;
                #pragma unroll
                for (int i = 0; i < 4; i++) {
                    const int r0 = warpM * 64 + i * 16 + gid;
                    af[nxt][i][0] = As[r0 * ASTRIDE + cb + tg];
                    af[nxt][i][1] = As[(r0 + 8) * ASTRIDE + cb + tg];
                    af[nxt][i][2] = As[r0 * ASTRIDE + cb + tg + 4];
                    af[nxt][i][3] = As[(r0 + 8) * ASTRIDE + cb + tg + 4];
                }
            }
            const int cb = ks * 8;
            #pragma unroll
            for (int j = 0; j < 8; j++) {
                const int col = warpN * 64 + j * 8 + gid;
                const uint32_t b0 = Bs[(cb + tg) * BSTRIDE + col];
                const uint32_t b1 = Bs[(cb + tg + 4) * BSTRIDE + col];
                #pragma unroll
                for (int i = 0; i < 4; i++)
                    mma8(c[i][j], af[cur][i][0], af[cur][i][1],
                         af[cur][i][2], af[cur][i][3], b0, b1);
            }
        }
        slot ^= 1;
    }
    #undef LOADST

    #pragma unroll
    for (int i = 0; i < 4; i++) {
        const int r0 = bm + warpM * 64 + i * 16 + gid;
        #pragma unroll
        for (int j = 0; j < 8; j++) {
            const int n0 = bn + warpN * 64 + j * 8 + tg * 2;
            #pragma unroll
            for (int h = 0; h < 2; h++) {
                const size_t off = (size_t)(r0 + 8 * h) * ldo + n0;
                float2 ov;
                if (ADD_X) {
                    float2 xv = *reinterpret_cast<const float2*>(Xg + off);
                    ov.x = fmaf(alpha, xv.x, c[i][j][2 * h + 0]);
                    ov.y = fmaf(alpha, xv.y, c[i][j][2 * h + 1]);
                } else if (ROUND_OUT) {
                    ov.x = __uint_as_float(f2tf32(c[i][j][2 * h + 0]));
                    ov.y = __uint_as_float(f2tf32(c[i][j][2 * h + 1]));
                } else {
                    ov.x = c[i][j][2 * h + 0];
                    ov.y = c[i][j][2 * h + 1];
                }
                *reinterpret_cast<float2*>(Og + off) = ov;
            }
        }
    }
}

// GEMM1: Y[16384][896] = Xr @ B1.  CTA 256x128 (4M x 2N), KT=64.
__global__ __launch_bounds__(256, 1)
void gemm1(const float* __restrict__ Xr, const float* __restrict__ B1,
           float* __restrict__ Y) {
    gemm_body<256, 128, 4, D_DIM / BKT, D_DIM, NPAD1, true, false>(
        Xr, B1, nullptr, nullptr, Y, NPAD1);
}

// GEMM2: Out = Y[:, :832] @ B2 + alpha * X.  CTA 128x256 (2M x 4N), KT=13.
__global__ __launch_bounds__(256, 1)
void gemm2(const float* __restrict__ Yg, const float* __restrict__ B2,
           const float* __restrict__ X, const float* __restrict__ alphap,
           float* __restrict__ Out) {
    gemm_body<128, 256, 2, KPAD / BKT, NPAD1, D_DIM, false, true>(
        Yg, B2, X, alphap, Out, D_DIM);
}

// ---------------------------------------------------------------- launch
extern "C" void kernel_launch(void* const* d_in, const int* in_sizes, int n_in,
                              void* d_out, int out_size) {
    const float* x     = (const float*)d_in[0];
    const float* U     = (const float*)d_in[1];
    const float* S     = (const float*)d_in[2];
    const float* V     = (const float*)d_in[3];
    const float* alpha = (const float*)d_in[4];
    float* out = (float*)d_out;

    float *Xrp, *Yp, *B1p, *B2p;
    cudaGetSymbolAddress((void**)&Xrp, g_Xr);
    cudaGetSymbolAddress((void**)&Yp,  g_Y);
    cudaGetSymbolAddress((void**)&B1p, g_B1);
    cudaGetSymbolAddress((void**)&B2p, g_B2);

    // smem: stage = BM*(BK+4) + BK*(BN+8) words, 2 stages
    constexpr int SMEM1 = 2 * (256 * 68 + 64 * 136) * 4;   // 208896
    constexpr int SMEM2 = 2 * (128 * 68 + 64 * 264) * 4;   // 204800
    cudaFuncSetAttribute(gemm1, cudaFuncAttributeMaxDynamicSharedMemorySize,
                         SMEM1);
    cudaFuncSetAttribute(gemm2, cudaFuncAttributeMaxDynamicSharedMemorySize,
                         SMEM2);

    prep_X<<<(M_TOTAL * (size_t)D_DIM / 4) / 256, 256>>>((const float4*)x,
                                                         (float4*)Xrp);
    prep_B1<<<((size_t)D_DIM * NPAD1) / 256, 256>>>(U, S, B1p);
    prep_B2<<<((size_t)KPAD * D_DIM) / 256, 256>>>(V, B2p);

    gemm1<<<dim3(NPAD1 / 128, M_TOTAL / 256), 256, SMEM1>>>(Xrp, B1p, Yp);
    gemm2<<<dim3(D_DIM / 256, M_TOTAL / 128), 256, SMEM2>>>(Yp, B2p, x,
                                                            alpha, out);
}

// round 8
// speedup vs baseline: 2.7798x; 1.7831x over previous
#include <cuda_runtime.h>
#include <cuda_fp16.h>
#include <cstdint>

// ---------------------------------------------------------------- shapes
#define M_TOTAL 16384
#define D_DIM   4096
#define RANK    819
#define KPAD    832          // gemm2 K (rank padded to 64)
#define NPAD1   896          // Y columns = 7 * 128

// ---------------------------------------------------------------- scratch
// All fp16 data stored as packed half2 words (low = even index).
__device__ uint32_t g_Xh[(size_t)M_TOTAL * (D_DIM / 2)];   // x, [m][k-pair]
__device__ uint32_t g_Yh[(size_t)M_TOTAL * (NPAD1 / 2)];   // Y, [m][n-pair]
__device__ uint32_t g_B1[(size_t)(D_DIM / 2) * NPAD1];     // (U*S), [k-pair][n]
__device__ uint32_t g_B2[(size_t)(KPAD / 2) * D_DIM];      // V,     [k-pair][n]

// ---------------------------------------------------------------- helpers
static __device__ __forceinline__ uint32_t s2u(const void* p) {
    uint32_t a;
    asm("{ .reg .u64 t; cvta.to.shared.u64 t, %1; cvt.u32.u64 %0, t; }"
        : "=r"(a) : "l"(p));
    return a;
}
static __device__ __forceinline__ uint32_t pkh2(float x, float y) {
    __half2 h = __floats2half2_rn(x, y);
    return *reinterpret_cast<uint32_t*>(&h);
}
static __device__ __forceinline__ void cp16(uint32_t dst, const void* src) {
    asm volatile("cp.async.cg.shared.global [%0], [%1], 16;"
                 :: "r"(dst), "l"(src) : "memory");
}
#define CP_COMMIT() asm volatile("cp.async.commit_group;" ::: "memory")
#define CP_WAIT1()  asm volatile("cp.async.wait_group 1;" ::: "memory")

static __device__ __forceinline__ void mma16(float c[4],
                                             uint32_t a0, uint32_t a1,
                                             uint32_t a2, uint32_t a3,
                                             uint32_t b0, uint32_t b1) {
    asm volatile(
        "mma.sync.aligned.m16n8k16.row.col.f32.f16.f16.f32 "
        "{%0,%1,%2,%3}, {%4,%5,%6,%7}, {%8,%9}, {%0,%1,%2,%3};"
        : "+f"(c[0]), "+f"(c[1]), "+f"(c[2]), "+f"(c[3])
        : "r"(a0), "r"(a1), "r"(a2), "r"(a3), "r"(b0), "r"(b1));
}

// ---------------------------------------------------------------- prep
__global__ void prep_X(const float4* __restrict__ X, uint2* __restrict__ Xh) {
    const size_t i = (size_t)blockIdx.x * blockDim.x + threadIdx.x;
    float4 v = X[i];
    uint2 o;
    o.x = pkh2(v.x, v.y);
    o.y = pkh2(v.z, v.w);
    Xh[i] = o;
}
__global__ void prep_B1(const float* __restrict__ U, const float* __restrict__ S,
                        uint32_t* __restrict__ B1) {
    const size_t id = (size_t)blockIdx.x * blockDim.x + threadIdx.x;
    const int n = (int)(id % NPAD1);
    const int kp = (int)(id / NPAD1);
    float v0 = 0.0f, v1 = 0.0f;
    if (n < RANK) {
        const float s = S[n];
        v0 = U[(size_t)(2 * kp) * RANK + n] * s;
        v1 = U[(size_t)(2 * kp + 1) * RANK + n] * s;
    }
    B1[id] = pkh2(v0, v1);
}
__global__ void prep_B2(const float* __restrict__ V, uint32_t* __restrict__ B2) {
    const size_t id = (size_t)blockIdx.x * blockDim.x + threadIdx.x;
    const int n = (int)(id & (D_DIM - 1));
    const int kp = (int)(id >> 12);
    const int k0 = 2 * kp;
    float v0 = 0.0f, v1 = 0.0f;
    if (k0 < RANK)     v0 = V[(size_t)k0 * D_DIM + n];
    if (k0 + 1 < RANK) v1 = V[(size_t)(k0 + 1) * D_DIM + n];
    B2[id] = pkh2(v0, v1);
}

// ---------------------------------------------------------------- GEMM body
// CTA tile BM x BN, 8 warps WM x (8/WM), warp tile 64x64.
// K tile = 64 halves = 32 words (BKW). 3 smem stages, wait_group 1.
// A smem: [BM][36] words ([m][k-pair]); B smem: [32][BN+8] words ([k-pair][n]).
#define BKW 32
#define STAGES 3

template <int BM, int BN, int WM, int KT, int LDAW, int LDBW,
          bool ROUND_OUT, bool ADD_X>
__device__ __forceinline__ void gemm_body(
    const uint32_t* __restrict__ Ag, const uint32_t* __restrict__ Bg,
    const float* __restrict__ Xg, const float* __restrict__ alphap,
    void* __restrict__ Og, int ldo)
{
    constexpr int ASTRIDE = BKW + 4;           // 36, conflict-free (4g+t)
    constexpr int BSTRIDE = BN + 8;            // conflict-free (8t+g)
    constexpr int AW = BM * ASTRIDE;
    constexpr int BW = BKW * BSTRIDE;
    constexpr int SW = AW + BW;
    constexpr int ACH = BM * (BKW / 4);        // A 16B chunks / stage
    constexpr int BCH = BKW * (BN / 4);        // B 16B chunks / stage
    constexpr int WN = 8 / WM;
    constexpr int ACR = BKW / 4;               // 8 A chunks per m-row
    constexpr int BCR = BN / 4;                // B chunks per kp-row

    extern __shared__ __align__(128) uint32_t sm[];
    const int tid = threadIdx.x;
    const int lane = tid & 31, wid = tid >> 5;
    const int gid = lane >> 2, tg = lane & 3;
    const int warpM = wid / WN, warpN = wid % WN;
    const int bm = blockIdx.y * BM, bn = blockIdx.x * BN;
    const uint32_t smu = s2u(sm);

    float alpha = 0.0f;
    if (ADD_X) alpha = *alphap;

    float c[4][8][4];
    #pragma unroll
    for (int i = 0; i < 4; i++)
        #pragma unroll
        for (int j = 0; j < 8; j++)
            #pragma unroll
            for (int v = 0; v < 4; v++) c[i][j][v] = 0.0f;

    #define LOADST(slot, kw0)                                                  \
    do {                                                                       \
        const uint32_t base = smu + (slot) * (SW * 4);                         \
        _Pragma("unroll")                                                      \
        for (int ii = 0; ii < (ACH + BCH) / 256; ii++) {                       \
            const int id = tid + 256 * ii;                                     \
            if (id < ACH) {                                                    \
                const int row = id / ACR, cc = id % ACR;                       \
                cp16(base + (row * ASTRIDE + cc * 4) * 4,                      \
                     Ag + (size_t)(bm + row) * LDAW + (kw0) + cc * 4);         \
            } else {                                                           \
                const int id2 = id - ACH;                                      \
                const int row = id2 / BCR, cc = id2 % BCR;                     \
                cp16(base + (AW + row * BSTRIDE + cc * 4) * 4,                 \
                     Bg + (size_t)((kw0) + row) * LDBW + bn + cc * 4);         \
            }                                                                  \
        }                                                                      \
    } while (0)

    LOADST(0, 0);    CP_COMMIT();
    LOADST(1, BKW);  CP_COMMIT();

    int slot = 0;
    for (int t = 0; t < KT; t++) {
        CP_WAIT1();            // tile t resident (only t+1 may be pending)
        __syncthreads();
        if (t + 2 < KT) {
            const int ns = (slot + 2 >= STAGES) ? slot + 2 - STAGES : slot + 2;
            LOADST(ns, (t + 2) * BKW);
        }
        CP_COMMIT();

        const uint32_t* As = sm + slot * SW;
        const uint32_t* Bs = As + AW;

        // A-fragment double-buffer across the 4 k16-steps
        uint32_t af[2][4][4];
        #pragma unroll
        for (int i = 0; i < 4; i++) {
            const int r0 = warpM * 64 + i * 16 + gid;
            af[0][i][0] = As[r0 * ASTRIDE + tg];
            af[0][i][1] = As[(r0 + 8) * ASTRIDE + tg];
            af[0][i][2] = As[r0 * ASTRIDE + tg + 4];
            af[0][i][3] = As[(r0 + 8) * ASTRIDE + tg + 4];
        }
        #pragma unroll
        for (int ks = 0; ks < 4; ks++) {
            const int cur = ks & 1, nxt = cur ^ 1;
            if (ks < 3) {
                const int cbw = (ks + 1) * 8;
                #pragma unroll
                for (int i = 0; i < 4; i++) {
                    const int r0 = warpM * 64 + i * 16 + gid;
                    af[nxt][i][0] = As[r0 * ASTRIDE + cbw + tg];
                    af[nxt][i][1] = As[(r0 + 8) * ASTRIDE + cbw + tg];
                    af[nxt][i][2] = As[r0 * ASTRIDE + cbw + tg + 4];
                    af[nxt][i][3] = As[(r0 + 8) * ASTRIDE + cbw + tg + 4];
                }
            }
            const int kp0 = ks * 8;
            #pragma unroll
            for (int j = 0; j < 8; j++) {
                const int col = warpN * 64 + j * 8 + gid;
                const uint32_t b0 = Bs[(kp0 + tg) * BSTRIDE + col];
                const uint32_t b1 = Bs[(kp0 + 4 + tg) * BSTRIDE + col];
                #pragma unroll
                for (int i = 0; i < 4; i++)
                    mma16(c[i][j], af[cur][i][0], af[cur][i][1],
                          af[cur][i][2], af[cur][i][3], b0, b1);
            }
        }
        slot = (slot + 1 >= STAGES) ? 0 : slot + 1;
    }
    #undef LOADST

    if (ROUND_OUT) {
        // pack to fp16 pairs: word (m, n/2)
        uint32_t* Yw = reinterpret_cast<uint32_t*>(Og);
        #pragma unroll
        for (int i = 0; i < 4; i++) {
            const int r0 = bm + warpM * 64 + i * 16 + gid;
            #pragma unroll
            for (int j = 0; j < 8; j++) {
                const int n0 = bn + warpN * 64 + j * 8 + tg * 2;
                Yw[(size_t)r0 * ldo + (n0 >> 1)]       = pkh2(c[i][j][0], c[i][j][1]);
                Yw[(size_t)(r0 + 8) * ldo + (n0 >> 1)] = pkh2(c[i][j][2], c[i][j][3]);
            }
        }
    } else {
        float* Of = reinterpret_cast<float*>(Og);
        #pragma unroll
        for (int i = 0; i < 4; i++) {
            const int r0 = bm + warpM * 64 + i * 16 + gid;
            #pragma unroll
            for (int j = 0; j < 8; j++) {
                const int n0 = bn + warpN * 64 + j * 8 + tg * 2;
                #pragma unroll
                for (int h = 0; h < 2; h++) {
                    const size_t off = (size_t)(r0 + 8 * h) * ldo + n0;
                    float2 ov;
                    if (ADD_X) {
                        float2 xv = *reinterpret_cast<const float2*>(Xg + off);
                        ov.x = fmaf(alpha, xv.x, c[i][j][2 * h + 0]);
                        ov.y = fmaf(alpha, xv.y, c[i][j][2 * h + 1]);
                    } else {
                        ov.x = c[i][j][2 * h + 0];
                        ov.y = c[i][j][2 * h + 1];
                    }
                    *reinterpret_cast<float2*>(Of + off) = ov;
                }
            }
        }
    }
}

// GEMM1: Yh[16384][896] = Xh @ B1.  CTA 256x128 (4M x 2N), KT = 4096/64 = 64.
__global__ __launch_bounds__(256, 1)
void gemm1(const uint32_t* __restrict__ Xh, const uint32_t* __restrict__ B1,
           uint32_t* __restrict__ Yh) {
    gemm_body<256, 128, 4, D_DIM / 64, D_DIM / 2, NPAD1, true, false>(
        Xh, B1, nullptr, nullptr, Yh, NPAD1 / 2);
}

// GEMM2: Out = Yh[:, :832] @ B2 + alpha * X.  CTA 128x256 (2M x 4N), KT = 13.
__global__ __launch_bounds__(256, 1)
void gemm2(const uint32_t* __restrict__ Yh, const uint32_t* __restrict__ B2,
           const float* __restrict__ X, const float* __restrict__ alphap,
           float* __restrict__ Out) {
    gemm_body<128, 256, 2, KPAD / 64, NPAD1 / 2, D_DIM, false, true>(
        Yh, B2, X, alphap, Out, D_DIM);
}

// ---------------------------------------------------------------- launch
extern "C" void kernel_launch(void* const* d_in, const int* in_sizes, int n_in,
                              void* d_out, int out_size) {
    const float* x     = (const float*)d_in[0];
    const float* U     = (const float*)d_in[1];
    const float* S     = (const float*)d_in[2];
    const float* V     = (const float*)d_in[3];
    const float* alpha = (const float*)d_in[4];
    float* out = (float*)d_out;

    uint32_t *Xhp, *Yhp, *B1p, *B2p;
    cudaGetSymbolAddress((void**)&Xhp, g_Xh);
    cudaGetSymbolAddress((void**)&Yhp, g_Yh);
    cudaGetSymbolAddress((void**)&B1p, g_B1);
    cudaGetSymbolAddress((void**)&B2p, g_B2);

    // smem: stage = (BM*36 + 32*(BN+8)) words, 3 stages
    constexpr int SMEM1 = STAGES * (256 * 36 + 32 * 136) * 4;   // 162816
    constexpr int SMEM2 = STAGES * (128 * 36 + 32 * 264) * 4;   // 156672
    cudaFuncSetAttribute(gemm1, cudaFuncAttributeMaxDynamicSharedMemorySize,
                         SMEM1);
    cudaFuncSetAttribute(gemm2, cudaFuncAttributeMaxDynamicSharedMemorySize,
                         SMEM2);

    prep_X<<<(M_TOTAL * (size_t)D_DIM / 4) / 256, 256>>>((const float4*)x,
                                                         (uint2*)Xhp);
    prep_B1<<<((size_t)(D_DIM / 2) * NPAD1) / 256, 256>>>(U, S, B1p);
    prep_B2<<<((size_t)(KPAD / 2) * D_DIM) / 256, 256>>>(V, B2p);

    gemm1<<<dim3(NPAD1 / 128, M_TOTAL / 256), 256, SMEM1>>>(Xhp, B1p, Yhp);
    gemm2<<<dim3(D_DIM / 256, M_TOTAL / 128), 256, SMEM2>>>(Yhp, B2p, x,
                                                            alpha, out);
}